// round 8
// baseline (speedup 1.0000x reference)
#include <cuda_runtime.h>
#include <cstdint>

#define S_  1024
#define B_  64
#define I_  256
#define H_  512
#define JW  16       // j-slice per CTA
#define NHG 32       // h-groups
#define NBG 8        // batch-groups (8 rows each)
#define NC  256      // 32 x 8 CTAs, 256 threads, 2 CTAs/SM

// ---------------- scratch (static __device__ — no allocation) ----------------
__device__ float  g_A[(size_t)S_ * B_ * H_];      // x @ W_in.T + b_in
__device__ float  g_C[(size_t)S_ * B_ * H_];      // x @ tau_w1[:,:I].T + b1
__device__ float  g_f[2][B_][H_];                 // tanh(u) exchange (dbl-buffered)
__device__ float4 g_part4[2][B_][NHG][2];         // 6 partial sums per (b, hg)
__device__ unsigned long long g_flag[NBG][NHG];   // per-bg p2p flags (monotonic)

// ---- packed fp32x2 helpers ----
#define FMA2(d, a, b) \
    asm("fma.rn.f32x2 %0, %1, %2, %0;" : "+l"(d) : "l"(a), "l"(b))

__device__ __forceinline__ unsigned long long pk2(float a, float b) {
    return (unsigned long long)__float_as_uint(a) |
           ((unsigned long long)__float_as_uint(b) << 32);
}
__device__ __forceinline__ float fold2(unsigned long long v) {
    return __uint_as_float((unsigned)v) + __uint_as_float((unsigned)(v >> 32));
}
// XOR swizzle on a 512-float row (16B granularity) -> conflict-free LDS.128
__device__ __forceinline__ int hswz(int f) {
    int u = f >> 2;
    u ^= (u >> 3) & 7;
    return (u << 2) | (f & 3);
}
__device__ __forceinline__ float tanh_f(float x) {
    float e = __expf(-2.f * fabsf(x));
    float t = __fdividef(1.f - e, 1.f + e);
    return copysignf(t, x);
}

// =============================================================================
// Kernel 1: time-parallel precompute GEMM (fp32x2). Unchanged.
// =============================================================================
__global__ __launch_bounds__(256, 2) void precompute_gemm(
    const float* __restrict__ x, const float* __restrict__ W_in,
    const float* __restrict__ b_in, const float* __restrict__ tau_w1,
    const float* __restrict__ tau_b1)
{
    __shared__ float xs[128][34];
    __shared__ float ws[64][34];

    const int tid    = threadIdx.x;
    const int m_base = blockIdx.x * 128;
    const int n_base = blockIdx.y * 64;
    const bool isA   = (n_base < 512);
    const int tm = tid >> 4, tn = tid & 15;
    const int m0 = tm * 8;

    unsigned long long c2[8][4];
    #pragma unroll
    for (int i = 0; i < 8; i++)
        #pragma unroll
        for (int j = 0; j < 4; j++) c2[i][j] = 0ULL;

    for (int kt = 0; kt < I_; kt += 32) {
        __syncthreads();
        #pragma unroll
        for (int it = 0; it < 4; it++) {                // x tile 128x32
            int q = it * 256 + tid;
            int row = q >> 3, kq = q & 7;
            int r = m_base + row;
            int tt = r >> 6, b = r & 63;
            float4 v = *(const float4*)(x + ((size_t)b * S_ + tt) * I_ + kt + kq * 4);
            *(float2*)&xs[row][kq * 4]     = make_float2(v.x, v.y);
            *(float2*)&xs[row][kq * 4 + 2] = make_float2(v.z, v.w);
        }
        #pragma unroll
        for (int it = 0; it < 2; it++) {                // w tile 64x32
            int q = it * 256 + tid;
            int row = q >> 3, kq = q & 7;
            int n = n_base + row;
            const float* wr = isA ? (W_in + (size_t)n * I_)
                                  : (tau_w1 + (size_t)(n - 512) * (I_ + H_));
            float4 v = *(const float4*)(wr + kt + kq * 4);
            *(float2*)&ws[row][kq * 4]     = make_float2(v.x, v.y);
            *(float2*)&ws[row][kq * 4 + 2] = make_float2(v.z, v.w);
        }
        __syncthreads();

        #pragma unroll
        for (int kk2 = 0; kk2 < 16; kk2++) {
            unsigned long long b2[4], a2[8];
            #pragma unroll
            for (int j = 0; j < 4; j++)
                b2[j] = *(const unsigned long long*)&ws[tn + 16 * j][kk2 * 2];
            #pragma unroll
            for (int i = 0; i < 8; i++)
                a2[i] = *(const unsigned long long*)&xs[m0 + i][kk2 * 2];
            #pragma unroll
            for (int i = 0; i < 8; i++)
                #pragma unroll
                for (int j = 0; j < 4; j++)
                    FMA2(c2[i][j], a2[i], b2[j]);
        }
    }

    #pragma unroll
    for (int j = 0; j < 4; j++) {
        int n = n_base + tn + 16 * j;
        float bias = isA ? b_in[n] : tau_b1[n - 512];
        #pragma unroll
        for (int i = 0; i < 8; i++) {
            int r = m_base + m0 + i;
            float v = fold2(c2[i][j]) + bias;
            if (isA) g_A[(size_t)r * H_ + n] = v;
            else     g_C[(size_t)r * H_ + (n - 512)] = v;
        }
    }
}

// =============================================================================
// Kernel 2: persistent scan, 256 CTAs x 256 threads, 2 CTAs/SM.
//   CTA (hg 0..31, bg 0..7): j-slice [hg*16,+16), batch rows [bg*8,+8).
//   Co-resident CTA pairs are from different bg -> independent streams whose
//   stalls (flag poll, L2 loads) overlap with the partner's FMA issue.
// =============================================================================
__global__ __launch_bounds__(256, 2) void liquid_recurrent(
    const float* __restrict__ h0,     const float* __restrict__ W_rec,
    const float* __restrict__ tau_w1, const float* __restrict__ tau_w2,
    const float* __restrict__ tau_b2, const float* __restrict__ gamma,
    const float* __restrict__ beta,
    float* __restrict__ out, float* __restrict__ hfin, float* __restrict__ tauh)
{
    __shared__ __align__(16) float h_s[8 * H_];     // swizzled h rows (16 KB)
    __shared__ float  pa_s[2][8][JW];               // A tiles, double-buffered
    __shared__ float  pc_s[2][8][JW];               // C tiles, double-buffered
    __shared__ float  val_s[8][2 * JW];             // f (0..15) / t_hid (16..31)
    __shared__ float4 stats_s[8];                   // {a, c, mean, rstd}
    __shared__ float  gam_s[H_], bet_s[H_];
    __shared__ float  w2_s[JW];

    const int tid  = threadIdx.x;
    const int hg   = blockIdx.x & 31;
    const int bg   = blockIdx.x >> 5;
    const int warp = tid >> 5, lane = tid & 31;
    const bool is_rec = (warp < 4);
    const int jlb  = (warp & 3) * 4;                // jl base for this warp

    const unsigned long long fbase = g_flag[bg][hg];

    // ---- recurrent weights -> registers as f32x2 k-pairs (64 floats) ----
    unsigned long long w2r[32];
    {
        #pragma unroll
        for (int op = 0; op < 4; op++) {
            int j = hg * JW + jlb + op;
            const float* wr = is_rec ? (W_rec + (size_t)j * H_)
                                     : (tau_w1 + (size_t)j * (I_ + H_) + I_);
            #pragma unroll
            for (int p4 = 0; p4 < 4; p4++) {
                float4 v = *(const float4*)(wr + lane * 16 + p4 * 4);
                w2r[op * 8 + p4 * 2]     = pk2(v.x, v.y);
                w2r[op * 8 + p4 * 2 + 1] = pk2(v.z, v.w);
            }
        }
    }
    const int s3 = (lane >> 1) & 7;
    int hoff[4];
    #pragma unroll
    for (int p4 = 0; p4 < 4; p4++) hoff[p4] = ((lane * 4 + p4) ^ s3) << 2;
    const int sw0 = hswz(tid);
    const int sw1 = hswz(tid + 256);
    const int sw_j = hswz(hg * JW + (lane & 15));

    gam_s[tid] = gamma[tid];         gam_s[tid + 256] = gamma[tid + 256];
    bet_s[tid] = beta[tid];          bet_s[tid + 256] = beta[tid + 256];
    if (tid < JW) w2_s[tid] = tau_w2[hg * JW + tid];
    const float tb2 = tau_b2[0];
    #pragma unroll
    for (int b = 0; b < 8; b++) {
        h_s[(b << 9) + sw0] = h0[(size_t)(bg * 8 + b) * H_ + tid];
        h_s[(b << 9) + sw1] = h0[(size_t)(bg * 8 + b) * H_ + tid + 256];
    }
    // prologue: tiles for t=0
    {
        int bb = (tid & 127) >> 4, jj = tid & 15;
        size_t base = ((size_t)(bg * 8 + bb)) * H_ + hg * JW + jj;
        if (tid < 128) pa_s[0][bb][jj] = g_A[base];
        else           pc_s[0][bb][jj] = g_C[base];
    }
    __syncthreads();

    const float gam0 = gam_s[tid], bet0 = bet_s[tid];
    const float gam1 = gam_s[tid + 256], bet1 = bet_s[tid + 256];

    for (int t = 0; t < S_; t++) {
        const int par = t & 1;

        // prefetch next step's A/C tile into registers
        float pf = 0.f;
        const int pt = t + 1;
        const int pbb = (tid & 127) >> 4, pjj = tid & 15;
        if (pt < S_) {
            size_t base = ((size_t)pt * B_ + bg * 8 + pbb) * H_ + hg * JW + pjj;
            pf = (tid < 128) ? g_A[base] : g_C[base];
        }

        // ---- GEMV: 4 outputs/warp, 16 k per lane, fp32x2 ----
        #pragma unroll
        for (int hb = 0; hb < 2; hb++) {
            unsigned long long acc2[16];
            #pragma unroll
            for (int i = 0; i < 16; i++) acc2[i] = 0ULL;
            #pragma unroll
            for (int b4 = 0; b4 < 4; b4++) {
                const float* hp = h_s + ((hb * 4 + b4) << 9);
                #pragma unroll
                for (int p4 = 0; p4 < 4; p4++) {
                    ulonglong2 hv = *(const ulonglong2*)(hp + hoff[p4]);
                    #pragma unroll
                    for (int op = 0; op < 4; op++) {
                        FMA2(acc2[op * 4 + b4], hv.x, w2r[op * 8 + p4 * 2]);
                        FMA2(acc2[op * 4 + b4], hv.y, w2r[op * 8 + p4 * 2 + 1]);
                    }
                }
            }
            float r[16];
            #pragma unroll
            for (int i = 0; i < 16; i++) r[i] = fold2(acc2[i]);
            {
                int up = lane & 16;
                #pragma unroll
                for (int i = 0; i < 8; i++) {
                    float snd = up ? r[i] : r[i + 8];
                    float kp  = up ? r[i + 8] : r[i];
                    r[i] = kp + __shfl_xor_sync(0xffffffffu, snd, 16);
                }
                up = lane & 8;
                #pragma unroll
                for (int i = 0; i < 4; i++) {
                    float snd = up ? r[i] : r[i + 4];
                    float kp  = up ? r[i + 4] : r[i];
                    r[i] = kp + __shfl_xor_sync(0xffffffffu, snd, 8);
                }
                up = lane & 4;
                #pragma unroll
                for (int i = 0; i < 2; i++) {
                    float snd = up ? r[i] : r[i + 2];
                    float kp  = up ? r[i + 2] : r[i];
                    r[i] = kp + __shfl_xor_sync(0xffffffffu, snd, 4);
                }
                {
                    int u2 = lane & 2;
                    float snd = u2 ? r[0] : r[1];
                    float kp  = u2 ? r[1] : r[0];
                    r[0] = kp + __shfl_xor_sync(0xffffffffu, snd, 2);
                }
                r[0] += __shfl_xor_sync(0xffffffffu, r[0], 1);
            }
            if (!(lane & 1)) {
                int idx = (lane >> 1) & 15;
                int op = idx >> 2, b4 = idx & 3;
                int bL = hb * 4 + b4, jl = jlb + op;
                float add = is_rec ? pa_s[par][bL][jl] : pc_s[par][bL][jl];
                val_s[bL][(is_rec ? 0 : JW) + jl] = tanh_f(r[0] + add);
            }
        }
        __syncthreads();

        // stash prefetched tile into the other buffer
        if (pt < S_) {
            if (tid < 128) pa_s[pt & 1][pbb][pjj] = pf;
            else           pc_s[pt & 1][pbb][pjj] = pf;
        }

        // publish f slice (8 rows x 16)
        if (tid < 128) {
            int b = tid >> 4, jj = tid & 15;
            g_f[par][bg * 8 + b][hg * JW + jj] = val_s[b][jj];
        }
        // per-row partial sums over this j-slice (warp = row)
        {
            int b = warp;
            float f = 0.f, th = 0.f, h = 0.f;
            if (lane < JW) {
                f  = val_s[b][lane];
                th = val_s[b][JW + lane];
                h  = h_s[(b << 9) + sw_j];
            }
            float p0 = f, p1 = f * f, p2 = h * f;
            float p3 = th * w2_s[lane & 15], p4v = h, p5 = h * h;
            #pragma unroll
            for (int off = 16; off; off >>= 1) {
                p0  += __shfl_down_sync(0xffffffffu, p0, off);
                p1  += __shfl_down_sync(0xffffffffu, p1, off);
                p2  += __shfl_down_sync(0xffffffffu, p2, off);
                p3  += __shfl_down_sync(0xffffffffu, p3, off);
                p4v += __shfl_down_sync(0xffffffffu, p4v, off);
                p5  += __shfl_down_sync(0xffffffffu, p5, off);
            }
            if (lane == 0) {
                g_part4[par][bg * 8 + b][hg][0] = make_float4(p0, p1, p2, p3);
                g_part4[par][bg * 8 + b][hg][1] = make_float4(p4v, p5, 0.f, 0.f);
            }
        }
        __syncthreads();                 // all publishes issued

        // ---- p2p sync: tid0 release-stores own flag; warp 0 polls 32 ----
        const unsigned long long tgt = fbase + (unsigned long long)(t + 1);
        if (warp == 0) {
            if (lane == 0)
                asm volatile("st.release.gpu.u64 [%0], %1;"
                             :: "l"(&g_flag[bg][hg]), "l"(tgt) : "memory");
            unsigned ok;
            do {
                unsigned long long v;
                asm volatile("ld.acquire.gpu.u64 %0, [%1];"
                             : "=l"(v) : "l"(&g_flag[bg][lane]) : "memory");
                ok = __all_sync(0xffffffffu, v >= tgt);
            } while (!ok);
        }
        __syncthreads();

        // ---- loads: partials (every warp = one row, 32 lanes = 32 hg) ----
        float4 u  = __ldcg(&g_part4[par][bg * 8 + warp][lane][0]);
        float4 v4 = __ldcg(&g_part4[par][bg * 8 + warp][lane][1]);
        float f_r0[8], f_r1[8];
        #pragma unroll
        for (int b = 0; b < 8; b++) {
            f_r0[b] = __ldcg(&g_f[par][bg * 8 + b][tid]);
            f_r1[b] = __ldcg(&g_f[par][bg * 8 + b][tid + 256]);
        }

        {
            float s0 = u.x, s1 = u.y, s2 = u.z, s3r = u.w;
            float s4 = v4.x, s5 = v4.y;
            #pragma unroll
            for (int off = 16; off; off >>= 1) {
                s0  += __shfl_down_sync(0xffffffffu, s0, off);
                s1  += __shfl_down_sync(0xffffffffu, s1, off);
                s2  += __shfl_down_sync(0xffffffffu, s2, off);
                s3r += __shfl_down_sync(0xffffffffu, s3r, off);
                s4  += __shfl_down_sync(0xffffffffu, s4, off);
                s5  += __shfl_down_sync(0xffffffffu, s5, off);
            }
            if (lane == 0) {
                int bG = bg * 8 + warp;
                float tau  = 1.f + 9.f / (1.f + __expf(-(s3r + tb2)));
                float cc   = 0.1f / tau;
                float aa   = 1.f - cc;
                float mean = (aa * s4 + cc * s0) * (1.f / 512.f);
                float ep2  = (aa * aa * s5 + 2.f * aa * cc * s2 + cc * cc * s1)
                             * (1.f / 512.f);
                float rstd = rsqrtf(ep2 - mean * mean + 1e-5f);
                stats_s[warp] = make_float4(aa, cc, mean, rstd);
                if (hg == 0) tauh[(size_t)bG * S_ + t] = tau;
            }
        }
        __syncthreads();

        // ---- reconstruct full h_new rows (2 elements/thread/row) ----
        const bool w0 = ((tid >> 4) == hg);
        const bool w1 = (((tid + 256) >> 4) == hg);
        #pragma unroll
        for (int b = 0; b < 8; b++) {
            float4 st = stats_s[b];
            int bG = bg * 8 + b;
            float h0v = h_s[(b << 9) + sw0];
            float h1v = h_s[(b << 9) + sw1];
            float hn0 = (st.x * h0v + st.y * f_r0[b] - st.z) * st.w * gam0 + bet0;
            float hn1 = (st.x * h1v + st.y * f_r1[b] - st.z) * st.w * gam1 + bet1;
            h_s[(b << 9) + sw0] = hn0;
            h_s[(b << 9) + sw1] = hn1;
            if (w0) {
                out[((size_t)bG * S_ + t) * H_ + tid] = hn0;
                if (t == S_ - 1) hfin[(size_t)bG * H_ + tid] = hn0;
            }
            if (w1) {
                out[((size_t)bG * S_ + t) * H_ + tid + 256] = hn1;
                if (t == S_ - 1) hfin[(size_t)bG * H_ + tid + 256] = hn1;
            }
        }
        __syncthreads();   // h_s reuse ordering for next step
    }
}

// =============================================================================
extern "C" void kernel_launch(void* const* d_in, const int* in_sizes, int n_in,
                              void* d_out, int out_size)
{
    const float* x     = (const float*)d_in[0];
    const float* h0    = (const float*)d_in[1];
    const float* W_in  = (const float*)d_in[2];
    const float* b_in  = (const float*)d_in[3];
    const float* W_rec = (const float*)d_in[4];
    const float* tw1   = (const float*)d_in[5];
    const float* tb1   = (const float*)d_in[6];
    const float* tw2   = (const float*)d_in[7];
    const float* tb2   = (const float*)d_in[8];
    const float* gamma = (const float*)d_in[9];
    const float* beta  = (const float*)d_in[10];

    float* out  = (float*)d_out;                       // [B, S, H]
    float* hfin = out + (size_t)B_ * S_ * H_;          // [B, H]
    float* tauh = hfin + (size_t)B_ * H_;              // [B, S, 1]

    dim3 g1(65536 / 128, 1024 / 64);                   // (512, 16)
    precompute_gemm<<<g1, 256>>>(x, W_in, b_in, tw1, tb1);
    liquid_recurrent<<<NC, 256>>>(h0, W_rec, tw1, tw2, tb2, gamma, beta,
                                  out, hfin, tauh);
}

// round 9
// speedup vs baseline: 1.9542x; 1.9542x over previous
#include <cuda_runtime.h>
#include <cstdint>

#define S_  1024
#define B_  64
#define I_  256
#define H_  512
#define NC  128      // persistent CTAs (16 h-groups x 8 b-groups)
#define NHG 16

// ---------------- scratch (static __device__ — no allocation) ----------------
__device__ float  g_A[(size_t)S_ * B_ * H_];      // x @ W_in.T + b_in      [t*64+b][j]
__device__ float  g_C[(size_t)S_ * B_ * H_];      // x @ tau_w1[:,:I].T+b1  [t*64+b][j]
__device__ float  g_f[2][B_][H_];                 // tanh(u) exchange, double-buffered
__device__ float4 g_part4[2][B_][NHG][2];         // 6 partial sums per (b, hgroup)
__device__ unsigned long long g_tickets;          // barrier arrivals (monotonic u64)

// ---- packed fp32x2 helpers (Blackwell dual-issue fp32) ----
#define FMA2(d, a, b) \
    asm("fma.rn.f32x2 %0, %1, %2, %0;" : "+l"(d) : "l"(a), "l"(b))

__device__ __forceinline__ unsigned long long pk2(float a, float b) {
    return (unsigned long long)__float_as_uint(a) |
           ((unsigned long long)__float_as_uint(b) << 32);
}
__device__ __forceinline__ float fold2(unsigned long long v) {
    return __uint_as_float((unsigned)v) + __uint_as_float((unsigned)(v >> 32));
}
// XOR swizzle on a 512-float h row (16B granularity) -> conflict-free LDS.128
__device__ __forceinline__ int hswz(int f) {
    int u = f >> 2;
    u ^= (u >> 3) & 7;
    return (u << 2) | (f & 3);
}
// fast tanh: (1 - e^{-2|x|}) / (1 + e^{-2|x|}), sign-restored (~1e-6 abs err)
__device__ __forceinline__ float tanh_f(float x) {
    float e = __expf(-2.f * fabsf(x));
    float t = __fdividef(1.f - e, 1.f + e);
    return copysignf(t, x);
}

// =============================================================================
// Kernel 1: time-parallel precompute GEMM (fp32x2). Unchanged from champion.
// =============================================================================
__global__ __launch_bounds__(256, 2) void precompute_gemm(
    const float* __restrict__ x, const float* __restrict__ W_in,
    const float* __restrict__ b_in, const float* __restrict__ tau_w1,
    const float* __restrict__ tau_b1)
{
    __shared__ float xs[128][34];
    __shared__ float ws[64][34];

    const int tid    = threadIdx.x;
    const int m_base = blockIdx.x * 128;
    const int n_base = blockIdx.y * 64;
    const bool isA   = (n_base < 512);
    const int tm = tid >> 4, tn = tid & 15;
    const int m0 = tm * 8;

    unsigned long long c2[8][4];
    #pragma unroll
    for (int i = 0; i < 8; i++)
        #pragma unroll
        for (int j = 0; j < 4; j++) c2[i][j] = 0ULL;

    for (int kt = 0; kt < I_; kt += 32) {
        __syncthreads();
        #pragma unroll
        for (int it = 0; it < 4; it++) {                // x tile 128x32
            int q = it * 256 + tid;
            int row = q >> 3, kq = q & 7;
            int r = m_base + row;
            int tt = r >> 6, b = r & 63;
            float4 v = *(const float4*)(x + ((size_t)b * S_ + tt) * I_ + kt + kq * 4);
            *(float2*)&xs[row][kq * 4]     = make_float2(v.x, v.y);
            *(float2*)&xs[row][kq * 4 + 2] = make_float2(v.z, v.w);
        }
        #pragma unroll
        for (int it = 0; it < 2; it++) {                // w tile 64x32
            int q = it * 256 + tid;
            int row = q >> 3, kq = q & 7;
            int n = n_base + row;
            const float* wr = isA ? (W_in + (size_t)n * I_)
                                  : (tau_w1 + (size_t)(n - 512) * (I_ + H_));
            float4 v = *(const float4*)(wr + kt + kq * 4);
            *(float2*)&ws[row][kq * 4]     = make_float2(v.x, v.y);
            *(float2*)&ws[row][kq * 4 + 2] = make_float2(v.z, v.w);
        }
        __syncthreads();

        #pragma unroll
        for (int kk2 = 0; kk2 < 16; kk2++) {
            unsigned long long b2[4], a2[8];
            #pragma unroll
            for (int j = 0; j < 4; j++)
                b2[j] = *(const unsigned long long*)&ws[tn + 16 * j][kk2 * 2];
            #pragma unroll
            for (int i = 0; i < 8; i++)
                a2[i] = *(const unsigned long long*)&xs[m0 + i][kk2 * 2];
            #pragma unroll
            for (int i = 0; i < 8; i++)
                #pragma unroll
                for (int j = 0; j < 4; j++)
                    FMA2(c2[i][j], a2[i], b2[j]);
        }
    }

    #pragma unroll
    for (int j = 0; j < 4; j++) {
        int n = n_base + tn + 16 * j;
        float bias = isA ? b_in[n] : tau_b1[n - 512];
        #pragma unroll
        for (int i = 0; i < 8; i++) {
            int r = m_base + m0 + i;
            float v = fold2(c2[i][j]) + bias;
            if (isA) g_A[(size_t)r * H_ + n] = v;
            else     g_C[(size_t)r * H_ + (n - 512)] = v;
        }
    }
}

// =============================================================================
// Kernel 2: persistent recurrent scan (CHAMPION structure: 128 CTAs x 512,
//   single ticket-counter barrier). Deltas vs champion: fast tanh, hoisted
//   post-barrier loads.
// =============================================================================
__device__ __forceinline__ void grid_barrier()
{
    __syncthreads();
    if (threadIdx.x == 0) {
        unsigned long long prev;
        asm volatile("atom.release.gpu.add.u64 %0, [%1], %2;"
                     : "=l"(prev) : "l"(&g_tickets), "l"(1ULL) : "memory");
        unsigned long long target = (prev & ~127ULL) + 128ULL;
        unsigned long long cur;
        do {
            asm volatile("ld.acquire.gpu.u64 %0, [%1];"
                         : "=l"(cur) : "l"(&g_tickets) : "memory");
        } while (cur < target);
    }
    __syncthreads();
}

__global__ __launch_bounds__(512, 1) void liquid_recurrent(
    const float* __restrict__ h0,     const float* __restrict__ W_rec,
    const float* __restrict__ tau_w1, const float* __restrict__ tau_w2,
    const float* __restrict__ tau_b2, const float* __restrict__ gamma,
    const float* __restrict__ beta,
    float* __restrict__ out, float* __restrict__ hfin, float* __restrict__ tauh)
{
    __shared__ __align__(16) float h_s[8 * H_];     // swizzled h rows (16 KB)
    __shared__ float  pa_s[2][8][32];               // A tiles, double-buffered
    __shared__ float  pc_s[2][8][32];               // C tiles, double-buffered
    __shared__ float  val_s[8][64];                 // f (o<32) / t_hid (o>=32)
    __shared__ float4 stats_s[8];                   // {a, c, mean, rstd}
    __shared__ float  gam_s[H_], bet_s[H_];
    __shared__ float  w2_s[32];

    const int tid  = threadIdx.x;
    const int hg   = blockIdx.x & 15;
    const int bg   = blockIdx.x >> 4;
    const int warp = tid >> 5, lane = tid & 31;
    const bool is_rec = (warp < 8);
    const int jlb  = (warp & 7) * 4;                // jl base for this warp

    // ---- recurrent weights -> registers as f32x2 k-pairs (64 regs) ----
    unsigned long long w2r[32];
    {
        #pragma unroll
        for (int op = 0; op < 4; op++) {
            int j = hg * 32 + jlb + op;
            const float* wr = is_rec ? (W_rec + (size_t)j * H_)
                                     : (tau_w1 + (size_t)j * (I_ + H_) + I_);
            #pragma unroll
            for (int p4 = 0; p4 < 4; p4++) {
                float4 v = *(const float4*)(wr + lane * 16 + p4 * 4);
                w2r[op * 8 + p4 * 2]     = pk2(v.x, v.y);
                w2r[op * 8 + p4 * 2 + 1] = pk2(v.z, v.w);
            }
        }
    }
    const int s3 = (lane >> 1) & 7;
    int hoff[4];
    #pragma unroll
    for (int p4 = 0; p4 < 4; p4++) hoff[p4] = ((lane * 4 + p4) ^ s3) << 2;
    const int sw_tid = hswz(tid);
    const int sw_j   = hswz(hg * 32 + lane);

    gam_s[tid] = gamma[tid];
    bet_s[tid] = beta[tid];
    if (tid < 32) w2_s[tid] = tau_w2[hg * 32 + tid];
    const float tb2 = tau_b2[0];
    #pragma unroll
    for (int b = 0; b < 8; b++)
        h_s[(b << 9) + sw_tid] = h0[(size_t)(bg * 8 + b) * H_ + tid];
    // prologue: tiles for t=0
    {
        int bb = (tid & 255) >> 5, jj = tid & 31;
        size_t base = ((size_t)(bg * 8 + bb)) * H_ + hg * 32 + jj;
        if (tid < 256) pa_s[0][bb][jj] = g_A[base];
        else           pc_s[0][bb][jj] = g_C[base];
    }
    __syncthreads();

    const float gam = gam_s[tid], bet = bet_s[tid];

    for (int t = 0; t < S_; t++) {
        const int par = t & 1;

        // prefetch next step's A/C tile into registers (DRAM latency hidden)
        float pf = 0.f;
        const int pt = t + 1;
        const int pbb = (tid & 255) >> 5, pjj = tid & 31;
        if (pt < S_) {
            size_t base = ((size_t)pt * B_ + bg * 8 + pbb) * H_ + hg * 32 + pjj;
            pf = (tid < 256) ? g_A[base] : g_C[base];
        }

        // ---- GEMV: 4 outputs/warp, 16 k per lane, fp32x2 ----
        #pragma unroll
        for (int hb = 0; hb < 2; hb++) {
            unsigned long long acc2[16];
            #pragma unroll
            for (int i = 0; i < 16; i++) acc2[i] = 0ULL;
            #pragma unroll
            for (int b4 = 0; b4 < 4; b4++) {
                const float* hp = h_s + ((hb * 4 + b4) << 9);
                #pragma unroll
                for (int p4 = 0; p4 < 4; p4++) {
                    ulonglong2 hv = *(const ulonglong2*)(hp + hoff[p4]);
                    #pragma unroll
                    for (int op = 0; op < 4; op++) {
                        FMA2(acc2[op * 4 + b4], hv.x, w2r[op * 8 + p4 * 2]);
                        FMA2(acc2[op * 4 + b4], hv.y, w2r[op * 8 + p4 * 2 + 1]);
                    }
                }
            }
            // fold k-pairs, butterfly-reduce 16 values over 32 lanes
            float r[16];
            #pragma unroll
            for (int i = 0; i < 16; i++) r[i] = fold2(acc2[i]);
            {
                int up = lane & 16;
                #pragma unroll
                for (int i = 0; i < 8; i++) {
                    float snd = up ? r[i] : r[i + 8];
                    float kp  = up ? r[i + 8] : r[i];
                    r[i] = kp + __shfl_xor_sync(0xffffffffu, snd, 16);
                }
                up = lane & 8;
                #pragma unroll
                for (int i = 0; i < 4; i++) {
                    float snd = up ? r[i] : r[i + 4];
                    float kp  = up ? r[i + 4] : r[i];
                    r[i] = kp + __shfl_xor_sync(0xffffffffu, snd, 8);
                }
                up = lane & 4;
                #pragma unroll
                for (int i = 0; i < 2; i++) {
                    float snd = up ? r[i] : r[i + 2];
                    float kp  = up ? r[i + 2] : r[i];
                    r[i] = kp + __shfl_xor_sync(0xffffffffu, snd, 4);
                }
                {
                    int u2 = lane & 2;
                    float snd = u2 ? r[0] : r[1];
                    float kp  = u2 ? r[1] : r[0];
                    r[0] = kp + __shfl_xor_sync(0xffffffffu, snd, 2);
                }
                r[0] += __shfl_xor_sync(0xffffffffu, r[0], 1);
            }
            if (!(lane & 1)) {
                int idx = (lane >> 1) & 15;
                int op = idx >> 2, b4 = idx & 3;
                int b = hb * 4 + b4, jl = jlb + op;
                float add = is_rec ? pa_s[par][b][jl] : pc_s[par][b][jl];
                val_s[b][(is_rec ? 0 : 32) + jl] = tanh_f(r[0] + add);
            }
        }
        __syncthreads();

        // stash prefetched tile into the other buffer
        if (pt < S_) {
            if (tid < 256) pa_s[pt & 1][pbb][pjj] = pf;
            else           pc_s[pt & 1][pbb][pjj] = pf;
        }

        // publish f slice (coalesced)
        if (tid < 256) {
            int b = tid >> 5, jj = tid & 31;
            g_f[par][bg * 8 + b][hg * 32 + jj] = val_s[b][jj];
        }
        // per-row partial sums over this j-slice (warp b)
        if (warp < 8) {
            int b = warp;
            float f  = val_s[b][lane];
            float th = val_s[b][lane + 32];
            float h  = h_s[(b << 9) + sw_j];
            float p0 = f, p1 = f * f, p2 = h * f;
            float p3 = th * w2_s[lane], p4 = h, p5 = h * h;
            #pragma unroll
            for (int off = 16; off; off >>= 1) {
                p0 += __shfl_down_sync(0xffffffffu, p0, off);
                p1 += __shfl_down_sync(0xffffffffu, p1, off);
                p2 += __shfl_down_sync(0xffffffffu, p2, off);
                p3 += __shfl_down_sync(0xffffffffu, p3, off);
                p4 += __shfl_down_sync(0xffffffffu, p4, off);
                p5 += __shfl_down_sync(0xffffffffu, p5, off);
            }
            if (lane == 0) {
                g_part4[par][bg * 8 + b][hg][0] = make_float4(p0, p1, p2, p3);
                g_part4[par][bg * 8 + b][hg][1] = make_float4(p4, p5, 0.f, 0.f);
            }
        }

        grid_barrier();     // the ONLY grid sync this step

        // ---- hoisted loads: partials first, then all f rows (overlap L2) ----
        float4 u  = make_float4(0.f, 0.f, 0.f, 0.f);
        float4 v4 = make_float4(0.f, 0.f, 0.f, 0.f);
        if (warp < 8 && lane < 16) {
            u  = __ldcg(&g_part4[par][bg * 8 + warp][lane][0]);
            v4 = __ldcg(&g_part4[par][bg * 8 + warp][lane][1]);
        }
        float f_r[8];
        #pragma unroll
        for (int b = 0; b < 8; b++)
            f_r[b] = __ldcg(&g_f[par][bg * 8 + b][tid]);

        // ---- row stats (redundant per b-group) ----
        if (warp < 8) {
            float s0 = u.x, s1 = u.y, s2 = u.z, s3r = u.w, s4 = v4.x, s5 = v4.y;
            #pragma unroll
            for (int off = 16; off; off >>= 1) {
                s0  += __shfl_down_sync(0xffffffffu, s0, off);
                s1  += __shfl_down_sync(0xffffffffu, s1, off);
                s2  += __shfl_down_sync(0xffffffffu, s2, off);
                s3r += __shfl_down_sync(0xffffffffu, s3r, off);
                s4  += __shfl_down_sync(0xffffffffu, s4, off);
                s5  += __shfl_down_sync(0xffffffffu, s5, off);
            }
            if (lane == 0) {
                int bG = bg * 8 + warp;
                float tau  = 1.f + 9.f / (1.f + __expf(-(s3r + tb2)));
                float cc   = 0.1f / tau;
                float aa   = 1.f - cc;
                float mean = (aa * s4 + cc * s0) * (1.f / 512.f);
                float ep2  = (aa * aa * s5 + 2.f * aa * cc * s2 + cc * cc * s1)
                             * (1.f / 512.f);
                float rstd = rsqrtf(ep2 - mean * mean + 1e-5f);
                stats_s[warp] = make_float4(aa, cc, mean, rstd);
                if (hg == 0) tauh[(size_t)bG * S_ + t] = tau;
            }
        }
        __syncthreads();

        // ---- reconstruct full h_new rows; write own output slice ----
        #pragma unroll
        for (int b = 0; b < 8; b++) {
            float4 st = stats_s[b];
            float h = h_s[(b << 9) + sw_tid];
            float p  = st.x * h + st.y * f_r[b];
            float hn = (p - st.z) * st.w * gam + bet;
            h_s[(b << 9) + sw_tid] = hn;
            if ((tid >> 5) == hg) {
                out[((size_t)(bg * 8 + b) * S_ + t) * H_ + tid] = hn;
                if (t == S_ - 1) hfin[(size_t)(bg * 8 + b) * H_ + tid] = hn;
            }
        }
        __syncthreads();   // h_s reuse ordering for next step
    }
}

// =============================================================================
extern "C" void kernel_launch(void* const* d_in, const int* in_sizes, int n_in,
                              void* d_out, int out_size)
{
    const float* x     = (const float*)d_in[0];
    const float* h0    = (const float*)d_in[1];
    const float* W_in  = (const float*)d_in[2];
    const float* b_in  = (const float*)d_in[3];
    const float* W_rec = (const float*)d_in[4];
    const float* tw1   = (const float*)d_in[5];
    const float* tb1   = (const float*)d_in[6];
    const float* tw2   = (const float*)d_in[7];
    const float* tb2   = (const float*)d_in[8];
    const float* gamma = (const float*)d_in[9];
    const float* beta  = (const float*)d_in[10];

    float* out  = (float*)d_out;                       // [B, S, H]
    float* hfin = out + (size_t)B_ * S_ * H_;          // [B, H]
    float* tauh = hfin + (size_t)B_ * H_;              // [B, S, 1]

    dim3 g1(65536 / 128, 1024 / 64);                   // (512, 16)
    precompute_gemm<<<g1, 256>>>(x, W_in, b_in, tw1, tb1);
    liquid_recurrent<<<NC, 512>>>(h0, W_rec, tw1, tw2, tb2, gamma, beta,
                                  out, hfin, tauh);
}